// round 6
// baseline (speedup 1.0000x reference)
#include <cuda_runtime.h>
#include <cuda_bf16.h>
#include <cstdint>
#include <math.h>

#define MROWS 8192   // B*T
#define KDIM  1024
#define TLEN  2048
#define HS    64

// ---------------- Scratch (device globals; alloc-free rule) ----------------
__device__ __nv_bfloat16 g_ahi[MROWS * KDIM];      // x hi/lo, later attn-out hi/lo
__device__ __nv_bfloat16 g_alo[MROWS * KDIM];
__device__ __nv_bfloat16 g_whi[4 * KDIM * KDIM];   // Wq,Wk,Wv,Wu hi
__device__ __nv_bfloat16 g_wlo[4 * KDIM * KDIM];   // lo
__device__ __nv_bfloat16 g_qh[MROWS * KDIM];
__device__ __nv_bfloat16 g_ql[MROWS * KDIM];
__device__ __nv_bfloat16 g_kh[MROWS * KDIM];
__device__ __nv_bfloat16 g_kl[MROWS * KDIM];
__device__ __nv_bfloat16 g_vh[MROWS * KDIM];
__device__ __nv_bfloat16 g_vl[MROWS * KDIM];

// ---------------- helpers ----------------
__device__ __forceinline__ uint32_t smem_u32(const void* p) {
    uint32_t a;
    asm("{ .reg .u64 t; cvta.to.shared.u64 t, %1; cvt.u32.u64 %0, t; }"
        : "=r"(a) : "l"(p));
    return a;
}

__device__ __forceinline__ void cp16(uint32_t dst, const void* src) {
    asm volatile("cp.async.cg.shared.global [%0], [%1], 16;" :: "r"(dst), "l"(src));
}

__device__ __forceinline__ void ldm_x4(uint32_t* r, uint32_t addr) {
    asm volatile("ldmatrix.sync.aligned.m8n8.x4.shared.b16 {%0,%1,%2,%3}, [%4];"
                 : "=r"(r[0]), "=r"(r[1]), "=r"(r[2]), "=r"(r[3]) : "r"(addr));
}

__device__ __forceinline__ void ldm_x4t(uint32_t* r, uint32_t addr) {
    asm volatile("ldmatrix.sync.aligned.m8n8.x4.trans.shared.b16 {%0,%1,%2,%3}, [%4];"
                 : "=r"(r[0]), "=r"(r[1]), "=r"(r[2]), "=r"(r[3]) : "r"(addr));
}

__device__ __forceinline__ void mma16816(float* c, const uint32_t* a,
                                         uint32_t b0, uint32_t b1) {
    asm volatile(
        "mma.sync.aligned.m16n8k16.row.col.f32.bf16.bf16.f32 "
        "{%0,%1,%2,%3}, {%4,%5,%6,%7}, {%8,%9}, {%0,%1,%2,%3};"
        : "+f"(c[0]), "+f"(c[1]), "+f"(c[2]), "+f"(c[3])
        : "r"(a[0]), "r"(a[1]), "r"(a[2]), "r"(a[3]), "r"(b0), "r"(b1));
}

// pack two floats into bf16 hi pair + residual lo pair
__device__ __forceinline__ void pack_hl(float x, float y, uint32_t& h, uint32_t& l) {
    __nv_bfloat162 hp = __floats2bfloat162_rn(x, y);
    float rx = x - __bfloat162float(hp.x);
    float ry = y - __bfloat162float(hp.y);
    __nv_bfloat162 lp = __floats2bfloat162_rn(rx, ry);
    h = *(uint32_t*)&hp;
    l = *(uint32_t*)&lp;
}

// ---------------------------------------------------------------------------
// Split fp32 -> bf16 hi + lo
// ---------------------------------------------------------------------------
__global__ __launch_bounds__(256) void split_bf16(const float* __restrict__ src,
                                                  __nv_bfloat16* __restrict__ hi,
                                                  __nv_bfloat16* __restrict__ lo,
                                                  int n4)
{
    int i = blockIdx.x * blockDim.x + threadIdx.x;
    if (i >= n4) return;
    float4 v = ((const float4*)src)[i];
    uint32_t h0, l0, h1, l1;
    pack_hl(v.x, v.y, h0, l0);
    pack_hl(v.z, v.w, h1, l1);
    uint2 hu = {h0, h1}, lu = {l0, l1};
    ((uint2*)hi)[i] = hu;
    ((uint2*)lo)[i] = lu;
}

// ---------------------------------------------------------------------------
// mma.sync bf16x3 GEMM: C = A @ B^T. A:(8192,1024), B:(1024,1024), K-major.
// 128x128 / CTA, K-chunk 32, 2-stage cp.async, 8 warps (2x4), warp 64x32.
// Output: either fp32 (+bias) to Cf, or bf16 hi/lo split to Chi/Clo.
// ---------------------------------------------------------------------------
#define BKC      32
#define ROWB     80                  // bytes per smem row (64 data + 16 pad)
#define TILE_SB  (128 * ROWB)
#define STAGE_SB (4 * TILE_SB)
#define SMEM_REQ (2 * STAGE_SB)      // 81920 B

__global__ __launch_bounds__(256) void gemm_mma(
    const __nv_bfloat16* __restrict__ Ahi, const __nv_bfloat16* __restrict__ Alo,
    const __nv_bfloat16* __restrict__ Bhi, const __nv_bfloat16* __restrict__ Blo,
    float* __restrict__ Cf, const float* __restrict__ bias,
    __nv_bfloat16* __restrict__ Chi, __nv_bfloat16* __restrict__ Clo)
{
    extern __shared__ char smem_raw[];
    const uint32_t sbase = smem_u32(smem_raw);

    const int tid  = threadIdx.x;
    const int wid  = tid >> 5;
    const int lane = tid & 31;
    const int wm   = wid >> 2;
    const int wn   = wid & 3;
    const int row0 = blockIdx.y * 128;
    const int col0 = blockIdx.x * 128;

    float acc[4][4][4];
#pragma unroll
    for (int i = 0; i < 4; i++)
#pragma unroll
        for (int j = 0; j < 4; j++)
#pragma unroll
            for (int t = 0; t < 4; t++) acc[i][j][t] = 0.f;

    auto load_chunk = [&](int c) {
        uint32_t st = sbase + (uint32_t)(c & 1) * STAGE_SB;
        int k0 = c * BKC;
#pragma unroll
        for (int it = 0; it < 2; it++) {
            int idx = it * 256 + tid;
            int r   = idx >> 2;
            int cb  = (idx & 3) << 4;
            uint32_t so = (uint32_t)(r * ROWB + cb);
            cp16(st + so,               (const char*)(Ahi + (size_t)(row0 + r) * KDIM + k0) + cb);
            cp16(st + TILE_SB + so,     (const char*)(Alo + (size_t)(row0 + r) * KDIM + k0) + cb);
            cp16(st + 2 * TILE_SB + so, (const char*)(Bhi + (size_t)(col0 + r) * KDIM + k0) + cb);
            cp16(st + 3 * TILE_SB + so, (const char*)(Blo + (size_t)(col0 + r) * KDIM + k0) + cb);
        }
        asm volatile("cp.async.commit_group;" ::: "memory");
    };

    load_chunk(0);
    load_chunk(1);

    const int NCHUNK = KDIM / BKC;
    const int lr = lane & 15;
    const int lc = lane >> 4;

    for (int c = 0; c < NCHUNK; c++) {
        if (c == NCHUNK - 1) asm volatile("cp.async.wait_group 0;" ::: "memory");
        else                 asm volatile("cp.async.wait_group 1;" ::: "memory");
        __syncthreads();

        uint32_t st = sbase + (uint32_t)(c & 1) * STAGE_SB;
        uint32_t aBase = st + (uint32_t)((wm * 64 + lr) * ROWB);
        uint32_t bBase = st + 2 * TILE_SB + (uint32_t)((wn * 32 + lr) * ROWB);

#pragma unroll
        for (int ks = 0; ks < BKC; ks += 16) {
            uint32_t colb = (uint32_t)((ks + 8 * lc) * 2);
            uint32_t ah[4][4], al[4][4], bh[2][4], bl[2][4];
#pragma unroll
            for (int mi = 0; mi < 4; mi++) {
                uint32_t ad = aBase + (uint32_t)(mi * 16 * ROWB) + colb;
                ldm_x4(ah[mi], ad);
                ldm_x4(al[mi], ad + TILE_SB);
            }
#pragma unroll
            for (int nj = 0; nj < 2; nj++) {
                uint32_t bd = bBase + (uint32_t)(nj * 16 * ROWB) + colb;
                ldm_x4(bh[nj], bd);
                ldm_x4(bl[nj], bd + TILE_SB);
            }
#pragma unroll
            for (int mi = 0; mi < 4; mi++)
#pragma unroll
                for (int ni = 0; ni < 4; ni++) {
                    int nj = ni >> 1, s = ni & 1;
                    mma16816(acc[mi][ni], ah[mi], bh[nj][s], bh[nj][s + 2]);
                    mma16816(acc[mi][ni], ah[mi], bl[nj][s], bl[nj][s + 2]);
                    mma16816(acc[mi][ni], al[mi], bh[nj][s], bh[nj][s + 2]);
                }
        }
        __syncthreads();
        if (c + 2 < NCHUNK) load_chunk(c + 2);
    }

#pragma unroll
    for (int ni = 0; ni < 4; ni++) {
        int col = col0 + wn * 32 + ni * 8 + 2 * (lane & 3);
#pragma unroll
        for (int mi = 0; mi < 4; mi++) {
            int r0 = row0 + wm * 64 + mi * 16 + (lane >> 2);
            if (Cf) {
                float b0 = bias ? bias[col] : 0.f;
                float b1 = bias ? bias[col + 1] : 0.f;
                float2 v0 = {acc[mi][ni][0] + b0, acc[mi][ni][1] + b1};
                float2 v1 = {acc[mi][ni][2] + b0, acc[mi][ni][3] + b1};
                *(float2*)(Cf + (size_t)r0 * KDIM + col) = v0;
                *(float2*)(Cf + (size_t)(r0 + 8) * KDIM + col) = v1;
            } else {
                uint32_t h0, l0, h1, l1;
                pack_hl(acc[mi][ni][0], acc[mi][ni][1], h0, l0);
                pack_hl(acc[mi][ni][2], acc[mi][ni][3], h1, l1);
                *(uint32_t*)(Chi + (size_t)r0 * KDIM + col) = h0;
                *(uint32_t*)(Clo + (size_t)r0 * KDIM + col) = l0;
                *(uint32_t*)(Chi + (size_t)(r0 + 8) * KDIM + col) = h1;
                *(uint32_t*)(Clo + (size_t)(r0 + 8) * KDIM + col) = l1;
            }
        }
    }
}

// ---------------------------------------------------------------------------
// Tensor-core flash attention (bf16x3). CTA = (128 queries, one b,h).
// 8 warps x 16 query rows. K/V tiles of 64 keys, double-buffered cp.async.
// QK^T: Q A-frags preloaded; K via ldmatrix. P reuses C-frag layout as A-frag.
// PV: V via ldmatrix.trans from [key][dim] layout.
// ---------------------------------------------------------------------------
#define ROWQ    144                  // smem row bytes: 64 bf16 + pad
#define QH_OFF  0
#define QL_OFF  18432                // 128*144
#define ST_OFF  36864
#define ST_SZ   36864                // KH|KL|VH|VL each 64*144=9216
#define SMEM_ATT 110592

__global__ __launch_bounds__(256) void attn_mma()
{
    extern __shared__ char smem_raw[];
    const uint32_t base = smem_u32(smem_raw);

    const int tid  = threadIdx.x;
    const int warp = tid >> 5;
    const int lane = tid & 31;
    const int qt = blockIdx.x;       // 0..15
    const int bh = blockIdx.y;       // 0..63
    const int b = bh >> 4;
    const int h = bh & 15;

    const size_t qrow0 = ((size_t)(b * TLEN + qt * 128)) * KDIM + h * HS;

    // ---- Q load (hi+lo), one group ----
#pragma unroll
    for (int it = 0; it < 8; it++) {
        int idx = it * 256 + tid;            // 0..2047
        int which = idx >> 10;               // 0=hi 1=lo
        int rem = idx & 1023;
        int r = rem >> 3;
        int ch = (rem & 7) << 4;
        const __nv_bfloat16* src = (which ? g_ql : g_qh) + qrow0 + (size_t)r * KDIM;
        cp16(base + (uint32_t)(which * QL_OFF + r * ROWQ + ch), (const char*)src + ch);
    }
    asm volatile("cp.async.commit_group;" ::: "memory");

    auto load_kv = [&](int c) {
        const __nv_bfloat16* arrs[4] = {g_kh, g_kl, g_vh, g_vl};
        uint32_t st = base + ST_OFF + (uint32_t)(c & 1) * ST_SZ;
        size_t krow0 = ((size_t)(b * TLEN + c * 64)) * KDIM + h * HS;
#pragma unroll
        for (int it = 0; it < 8; it++) {
            int idx = it * 256 + tid;        // 0..2047
            int which = idx >> 9;            // 0..3
            int rem = idx & 511;
            int r = rem >> 3;
            int ch = (rem & 7) << 4;
            const __nv_bfloat16* src = arrs[which] + krow0 + (size_t)r * KDIM;
            cp16(st + (uint32_t)(which * 9216 + r * ROWQ + ch), (const char*)src + ch);
        }
        asm volatile("cp.async.commit_group;" ::: "memory");
    };

    load_kv(0);
    load_kv(1);

    asm volatile("cp.async.wait_group 2;" ::: "memory");   // Q ready
    __syncthreads();

    // ---- preload Q fragments (per warp, 16 rows x 64 dims, hi+lo) ----
    uint32_t qfh[4][4], qfl[4][4];
    {
        uint32_t qb = base + (uint32_t)((warp * 16 + (lane & 15)) * ROWQ);
#pragma unroll
        for (int ks = 0; ks < 4; ks++) {
            uint32_t colb = (uint32_t)(ks * 32 + (lane >> 4) * 16);
            ldm_x4(qfh[ks], qb + colb);
            ldm_x4(qfl[ks], qb + QL_OFF + colb);
        }
    }

    const float scale = 0.03125f;    // 1/sqrt(1024)
    float m0 = -1e30f, m1 = -1e30f, l0 = 0.f, l1 = 0.f;
    float O[8][4];
#pragma unroll
    for (int t = 0; t < 8; t++)
#pragma unroll
        for (int e = 0; e < 4; e++) O[t][e] = 0.f;

    for (int c = 0; c < 32; c++) {
        if (c == 31) asm volatile("cp.async.wait_group 0;" ::: "memory");
        else         asm volatile("cp.async.wait_group 1;" ::: "memory");
        __syncthreads();

        uint32_t st = base + ST_OFF + (uint32_t)(c & 1) * ST_SZ;

        // ---- S = Q K^T ----
        float S[8][4];
#pragma unroll
        for (int t = 0; t < 8; t++)
#pragma unroll
            for (int e = 0; e < 4; e++) S[t][e] = 0.f;

#pragma unroll
        for (int ks = 0; ks < 4; ks++) {
            uint32_t kh4[4][4], kl4[4][4];
            uint32_t colb = (uint32_t)(ks * 32 + (lane >> 4) * 16);
#pragma unroll
            for (int ng = 0; ng < 4; ng++) {
                uint32_t ad = st + (uint32_t)((ng * 16 + (lane & 15)) * ROWQ) + colb;
                ldm_x4(kh4[ng], ad);
                ldm_x4(kl4[ng], ad + 9216);
            }
#pragma unroll
            for (int ng = 0; ng < 4; ng++)
#pragma unroll
                for (int s = 0; s < 2; s++) {
                    int nt = ng * 2 + s;
                    mma16816(S[nt], qfh[ks], kh4[ng][s], kh4[ng][s + 2]);
                    mma16816(S[nt], qfh[ks], kl4[ng][s], kl4[ng][s + 2]);
                    mma16816(S[nt], qfl[ks], kh4[ng][s], kh4[ng][s + 2]);
                }
        }

        // ---- online softmax (rows r = lane>>2 and r+8) ----
        float mx0 = -1e30f, mx1 = -1e30f;
#pragma unroll
        for (int t = 0; t < 8; t++) {
            S[t][0] *= scale; S[t][1] *= scale; S[t][2] *= scale; S[t][3] *= scale;
            mx0 = fmaxf(mx0, fmaxf(S[t][0], S[t][1]));
            mx1 = fmaxf(mx1, fmaxf(S[t][2], S[t][3]));
        }
        mx0 = fmaxf(mx0, __shfl_xor_sync(0xffffffffu, mx0, 1));
        mx0 = fmaxf(mx0, __shfl_xor_sync(0xffffffffu, mx0, 2));
        mx1 = fmaxf(mx1, __shfl_xor_sync(0xffffffffu, mx1, 1));
        mx1 = fmaxf(mx1, __shfl_xor_sync(0xffffffffu, mx1, 2));
        float mn0 = fmaxf(m0, mx0), mn1 = fmaxf(m1, mx1);
        float a0 = __expf(m0 - mn0), a1 = __expf(m1 - mn1);
        m0 = mn0; m1 = mn1;
        float sum0 = 0.f, sum1 = 0.f;
#pragma unroll
        for (int t = 0; t < 8; t++) {
            S[t][0] = __expf(S[t][0] - m0);
            S[t][1] = __expf(S[t][1] - m0);
            S[t][2] = __expf(S[t][2] - m1);
            S[t][3] = __expf(S[t][3] - m1);
            sum0 += S[t][0] + S[t][1];
            sum1 += S[t][2] + S[t][3];
        }
        sum0 += __shfl_xor_sync(0xffffffffu, sum0, 1);
        sum0 += __shfl_xor_sync(0xffffffffu, sum0, 2);
        sum1 += __shfl_xor_sync(0xffffffffu, sum1, 1);
        sum1 += __shfl_xor_sync(0xffffffffu, sum1, 2);
        l0 = l0 * a0 + sum0;
        l1 = l1 * a1 + sum1;
#pragma unroll
        for (int t = 0; t < 8; t++) {
            O[t][0] *= a0; O[t][1] *= a0; O[t][2] *= a1; O[t][3] *= a1;
        }

        // ---- P -> A fragments (C-frag layout == A-frag layout) ----
        uint32_t pah[4][4], pal[4][4];
#pragma unroll
        for (int j = 0; j < 4; j++) {
            pack_hl(S[2 * j][0],     S[2 * j][1],     pah[j][0], pal[j][0]);
            pack_hl(S[2 * j][2],     S[2 * j][3],     pah[j][1], pal[j][1]);
            pack_hl(S[2 * j + 1][0], S[2 * j + 1][1], pah[j][2], pal[j][2]);
            pack_hl(S[2 * j + 1][2], S[2 * j + 1][3], pah[j][3], pal[j][3]);
        }

        // ---- O += P V  (V via ldmatrix.trans) ----
#pragma unroll
        for (int ks = 0; ks < 4; ks++) {
            uint32_t vh4[4][4], vl4[4][4];
            uint32_t krow = (uint32_t)(ks * 16 + (lane & 7) + ((lane & 16) >> 1));
            uint32_t nb = (uint32_t)(((lane >> 3) & 1) * 16);
#pragma unroll
            for (int dg = 0; dg < 4; dg++) {
                uint32_t ad = st + 18432 + krow * ROWQ + (uint32_t)(dg * 32) + nb;
                ldm_x4t(vh4[dg], ad);
                ldm_x4t(vl4[dg], ad + 9216);
            }
#pragma unroll
            for (int dg = 0; dg < 4; dg++)
#pragma unroll
                for (int s = 0; s < 2; s++) {
                    int nt = dg * 2 + s;
                    mma16816(O[nt], pah[ks], vh4[dg][s], vh4[dg][s + 2]);
                    mma16816(O[nt], pah[ks], vl4[dg][s], vl4[dg][s + 2]);
                    mma16816(O[nt], pal[ks], vh4[dg][s], vh4[dg][s + 2]);
                }
        }

        __syncthreads();
        if (c + 2 < 32) load_kv(c + 2);
    }

    // ---- epilogue: normalize, split hi/lo, store ----
    float inv0 = 1.f / l0, inv1 = 1.f / l1;
    size_t orow0 = ((size_t)(b * TLEN + qt * 128 + warp * 16 + (lane >> 2))) * KDIM + h * HS;
    size_t orow1 = orow0 + (size_t)8 * KDIM;
#pragma unroll
    for (int t = 0; t < 8; t++) {
        int col = t * 8 + 2 * (lane & 3);
        uint32_t h0, l0u, h1, l1u;
        pack_hl(O[t][0] * inv0, O[t][1] * inv0, h0, l0u);
        pack_hl(O[t][2] * inv1, O[t][3] * inv1, h1, l1u);
        *(uint32_t*)(g_ahi + orow0 + col) = h0;
        *(uint32_t*)(g_alo + orow0 + col) = l0u;
        *(uint32_t*)(g_ahi + orow1 + col) = h1;
        *(uint32_t*)(g_alo + orow1 + col) = l1u;
    }
}

// ---------------------------------------------------------------------------
extern "C" void kernel_launch(void* const* d_in, const int* in_sizes, int n_in,
                              void* d_out, int out_size)
{
    const float* x  = (const float*)d_in[0];
    const float* Wk = (const float*)d_in[1];
    const float* Wq = (const float*)d_in[2];
    const float* Wv = (const float*)d_in[3];
    const float* Wu = (const float*)d_in[4];
    const float* bu = (const float*)d_in[5];
    float* out = (float*)d_out;

    cudaFuncSetAttribute(gemm_mma, cudaFuncAttributeMaxDynamicSharedMemorySize, SMEM_REQ);
    cudaFuncSetAttribute(attn_mma, cudaFuncAttributeMaxDynamicSharedMemorySize, SMEM_ATT);

    __nv_bfloat16 *ahi, *alo, *whi, *wlo, *qh, *ql, *kh, *kl, *vh, *vl;
    cudaGetSymbolAddress((void**)&ahi, g_ahi);
    cudaGetSymbolAddress((void**)&alo, g_alo);
    cudaGetSymbolAddress((void**)&whi, g_whi);
    cudaGetSymbolAddress((void**)&wlo, g_wlo);
    cudaGetSymbolAddress((void**)&qh, g_qh);
    cudaGetSymbolAddress((void**)&ql, g_ql);
    cudaGetSymbolAddress((void**)&kh, g_kh);
    cudaGetSymbolAddress((void**)&kl, g_kl);
    cudaGetSymbolAddress((void**)&vh, g_vh);
    cudaGetSymbolAddress((void**)&vl, g_vl);

    const int nx4 = MROWS * KDIM / 4;
    const int nw4 = KDIM * KDIM / 4;
    const size_t WSZ = (size_t)KDIM * KDIM;

    split_bf16<<<nx4 / 256, 256>>>(x, ahi, alo, nx4);
    split_bf16<<<nw4 / 256, 256>>>(Wq, whi + 0 * WSZ, wlo + 0 * WSZ, nw4);
    split_bf16<<<nw4 / 256, 256>>>(Wk, whi + 1 * WSZ, wlo + 1 * WSZ, nw4);
    split_bf16<<<nw4 / 256, 256>>>(Wv, whi + 2 * WSZ, wlo + 2 * WSZ, nw4);
    split_bf16<<<nw4 / 256, 256>>>(Wu, whi + 3 * WSZ, wlo + 3 * WSZ, nw4);

    dim3 gg(KDIM / 128, MROWS / 128);   // (8, 64)
    gemm_mma<<<gg, 256, SMEM_REQ>>>(ahi, alo, whi + 0 * WSZ, wlo + 0 * WSZ,
                                    nullptr, nullptr, qh, ql);
    gemm_mma<<<gg, 256, SMEM_REQ>>>(ahi, alo, whi + 1 * WSZ, wlo + 1 * WSZ,
                                    nullptr, nullptr, kh, kl);
    gemm_mma<<<gg, 256, SMEM_REQ>>>(ahi, alo, whi + 2 * WSZ, wlo + 2 * WSZ,
                                    nullptr, nullptr, vh, vl);

    attn_mma<<<dim3(16, 64), 256, SMEM_ATT>>>();

    gemm_mma<<<gg, 256, SMEM_REQ>>>(ahi, alo, whi + 3 * WSZ, wlo + 3 * WSZ,
                                    out, bu, nullptr, nullptr);
}